// round 15
// baseline (speedup 1.0000x reference)
#include <cuda_runtime.h>
#include <cuda_fp16.h>
#include <stdint.h>
#include <math.h>

#define NB 256   // batch
#define NI 128   // input capsules
#define DD 256   // input feature dim
#define NO 32    // output capsules
#define HH 64    // in_dim == out_dim

// ---- scratch (device globals; no allocation allowed) ----
__device__ __half g_votes[(size_t)NB * NI * NO * HH];  // [n][i][o][h] fp16, 134 MB
__device__ __half g_uh[(size_t)NB * NI * HH];          // squashed u fp16, 4 MB
__device__ float  g_ai[NB * NI];                       // ||u||

__device__ __forceinline__ uint32_t smem_u32(const void* p) {
    uint32_t a;
    asm("{ .reg .u64 t; cvta.to.shared.u64 t, %1; cvt.u32.u64 %0, t; }" : "=r"(a) : "l"(p));
    return a;
}

#define CP_ASYNC16(dst_u32, src_ptr) \
    asm volatile("cp.async.cg.shared.global [%0], [%1], 16;" :: "r"(dst_u32), "l"(src_ptr))
#define CP_ASYNC_COMMIT() asm volatile("cp.async.commit_group;")
#define CP_ASYNC_WAIT0()  asm volatile("cp.async.wait_group 0;")

// ============================================================
// K1 (HMMA, hi/lo fp16 = fp32-accurate), M-tile = 128, cp.async staged.
// ============================================================
__global__ __launch_bounds__(128) void k_u(const float* __restrict__ x,
                                           const float* __restrict__ Wcap,
                                           const float* __restrict__ Bcap) {
    __shared__ __align__(16) __half sAhi[128 * 64];
    __shared__ __align__(16) __half sAlo[128 * 64];
    __shared__ __align__(16) __half sBhi[64 * 64];
    __shared__ __align__(16) __half sBlo[64 * 64];
    extern __shared__ __align__(16) unsigned char rawbuf[];   // 48 KB dynamic
    float* rawX = reinterpret_cast<float*>(rawbuf);
    float* rawW = reinterpret_cast<float*>(rawbuf + 32768);

    const int i  = blockIdx.y;
    const int n0 = blockIdx.x * 128;
    const int t  = threadIdx.x, w = t >> 5, l = t & 31;

    __half2* sAhi2 = reinterpret_cast<__half2*>(sAhi);
    __half2* sAlo2 = reinterpret_cast<__half2*>(sAlo);
    __half2* sBhi2 = reinterpret_cast<__half2*>(sBhi);
    __half2* sBlo2 = reinterpret_cast<__half2*>(sBlo);
    const uint32_t aHi = smem_u32(sAhi), aLo = smem_u32(sAlo);
    const uint32_t bHi = smem_u32(sBhi), bLo = smem_u32(sBlo);
    const uint32_t rX = smem_u32(rawX), rW = smem_u32(rawW);

    // prefetch kc = 0
    {
        #pragma unroll
        for (int j = 0; j < 16; ++j) {
            const int idx = t + j * 128;
            const int r = idx >> 4, c4 = idx & 15;
            CP_ASYNC16(rX + idx * 16,
                       reinterpret_cast<const uint4*>(
                           x + ((size_t)(n0 + r) * NI + i) * DD) + c4);
        }
        #pragma unroll
        for (int j = 0; j < 8; ++j) {
            const int idx = t + j * 128;
            const int d = idx >> 4, c4 = idx & 15;
            CP_ASYNC16(rW + idx * 16,
                       reinterpret_cast<const uint4*>(
                           Wcap + (size_t)i * DD * HH + (size_t)d * HH) + c4);
        }
        CP_ASYNC_COMMIT();
    }

    float acc[2][8][4];
    #pragma unroll
    for (int mt = 0; mt < 2; ++mt)
        #pragma unroll
        for (int nt = 0; nt < 8; ++nt) {
            acc[mt][nt][0] = 0.f; acc[mt][nt][1] = 0.f;
            acc[mt][nt][2] = 0.f; acc[mt][nt][3] = 0.f;
        }

    for (int kc = 0; kc < 4; ++kc) {
        CP_ASYNC_WAIT0();
        __syncthreads();

        {
            const float2* xr = reinterpret_cast<const float2*>(rawX);
            #pragma unroll
            for (int j = 0; j < 32; ++j) {
                const int idx = t + j * 128;
                const int r = idx >> 5, d2 = idx & 31;
                const float2 v = xr[idx];
                const __half h0 = __float2half_rn(v.x), h1 = __float2half_rn(v.y);
                const __half l0 = __float2half_rn(v.x - __half2float(h0));
                const __half l1 = __float2half_rn(v.y - __half2float(h1));
                const int c = d2 >> 2;
                const int sidx = r * 32 + ((c ^ (r & 7)) << 2) + (d2 & 3);
                sAhi2[sidx] = __halves2half2(h0, h1);
                sAlo2[sidx] = __halves2half2(l0, l1);
            }
            const float2* wr = reinterpret_cast<const float2*>(rawW);
            #pragma unroll
            for (int j = 0; j < 16; ++j) {
                const int idx = t + j * 128;
                const int d = idx >> 5, h2 = idx & 31;
                const float2 v = wr[idx];
                const __half h0 = __float2half_rn(v.x), h1 = __float2half_rn(v.y);
                const __half l0 = __float2half_rn(v.x - __half2float(h0));
                const __half l1 = __float2half_rn(v.y - __half2float(h1));
                const int c = h2 >> 2;
                const int sidx = d * 32 + ((c ^ (d & 7)) << 2) + (h2 & 3);
                sBhi2[sidx] = __halves2half2(h0, h1);
                sBlo2[sidx] = __halves2half2(l0, l1);
            }
        }
        __syncthreads();

        if (kc < 3) {
            const int ko = (kc + 1) * 64;
            #pragma unroll
            for (int j = 0; j < 16; ++j) {
                const int idx = t + j * 128;
                const int r = idx >> 4, c4 = idx & 15;
                CP_ASYNC16(rX + idx * 16,
                           reinterpret_cast<const uint4*>(
                               x + ((size_t)(n0 + r) * NI + i) * DD + ko) + c4);
            }
            #pragma unroll
            for (int j = 0; j < 8; ++j) {
                const int idx = t + j * 128;
                const int d = idx >> 4, c4 = idx & 15;
                CP_ASYNC16(rW + idx * 16,
                           reinterpret_cast<const uint4*>(
                               Wcap + (size_t)i * DD * HH + (size_t)(ko + d) * HH) + c4);
            }
            CP_ASYNC_COMMIT();
        }

        #pragma unroll
        for (int k = 0; k < 4; ++k) {
            uint32_t ah[2][4], al[2][4];
            #pragma unroll
            for (int mt = 0; mt < 2; ++mt) {
                const int row = w * 32 + mt * 16 + (l & 15);
                const int ch  = (k * 2 + (l >> 4)) ^ (row & 7);
                const uint32_t off = row * 128 + ch * 16;
                asm volatile("ldmatrix.sync.aligned.m8n8.x4.shared.b16 {%0,%1,%2,%3}, [%4];"
                    : "=r"(ah[mt][0]), "=r"(ah[mt][1]), "=r"(ah[mt][2]), "=r"(ah[mt][3])
                    : "r"(aHi + off));
                asm volatile("ldmatrix.sync.aligned.m8n8.x4.shared.b16 {%0,%1,%2,%3}, [%4];"
                    : "=r"(al[mt][0]), "=r"(al[mt][1]), "=r"(al[mt][2]), "=r"(al[mt][3])
                    : "r"(aLo + off));
            }
            #pragma unroll
            for (int nt = 0; nt < 8; ++nt) {
                const int d  = k * 16 + (l & 15);
                const int ch = nt ^ (d & 7);
                const uint32_t off = d * 128 + ch * 16;
                uint32_t bh0, bh1, bl0, bl1;
                asm volatile("ldmatrix.sync.aligned.m8n8.x2.trans.shared.b16 {%0,%1}, [%2];"
                    : "=r"(bh0), "=r"(bh1) : "r"(bHi + off));
                asm volatile("ldmatrix.sync.aligned.m8n8.x2.trans.shared.b16 {%0,%1}, [%2];"
                    : "=r"(bl0), "=r"(bl1) : "r"(bLo + off));
                #pragma unroll
                for (int mt = 0; mt < 2; ++mt) {
                    asm volatile("mma.sync.aligned.m16n8k16.row.col.f32.f16.f16.f32 "
                        "{%0,%1,%2,%3}, {%4,%5,%6,%7}, {%8,%9}, {%0,%1,%2,%3};"
                        : "+f"(acc[mt][nt][0]), "+f"(acc[mt][nt][1]),
                          "+f"(acc[mt][nt][2]), "+f"(acc[mt][nt][3])
                        : "r"(ah[mt][0]), "r"(ah[mt][1]), "r"(ah[mt][2]), "r"(ah[mt][3]),
                          "r"(bh0), "r"(bh1));
                    asm volatile("mma.sync.aligned.m16n8k16.row.col.f32.f16.f16.f32 "
                        "{%0,%1,%2,%3}, {%4,%5,%6,%7}, {%8,%9}, {%0,%1,%2,%3};"
                        : "+f"(acc[mt][nt][0]), "+f"(acc[mt][nt][1]),
                          "+f"(acc[mt][nt][2]), "+f"(acc[mt][nt][3])
                        : "r"(ah[mt][0]), "r"(ah[mt][1]), "r"(ah[mt][2]), "r"(ah[mt][3]),
                          "r"(bl0), "r"(bl1));
                    asm volatile("mma.sync.aligned.m16n8k16.row.col.f32.f16.f16.f32 "
                        "{%0,%1,%2,%3}, {%4,%5,%6,%7}, {%8,%9}, {%0,%1,%2,%3};"
                        : "+f"(acc[mt][nt][0]), "+f"(acc[mt][nt][1]),
                          "+f"(acc[mt][nt][2]), "+f"(acc[mt][nt][3])
                        : "r"(al[mt][0]), "r"(al[mt][1]), "r"(al[mt][2]), "r"(al[mt][3]),
                          "r"(bh0), "r"(bh1));
                }
            }
        }
    }

    #pragma unroll
    for (int mt = 0; mt < 2; ++mt) {
        const int r = w * 32 + mt * 16 + (l >> 2);
        float q0 = 0.f, q1 = 0.f;
        #pragma unroll
        for (int nt = 0; nt < 8; ++nt) {
            const float2 bv = *reinterpret_cast<const float2*>(
                Bcap + i * HH + nt * 8 + (l & 3) * 2);
            acc[mt][nt][0] += bv.x; acc[mt][nt][1] += bv.y;
            acc[mt][nt][2] += bv.x; acc[mt][nt][3] += bv.y;
            q0 += acc[mt][nt][0] * acc[mt][nt][0] + acc[mt][nt][1] * acc[mt][nt][1];
            q1 += acc[mt][nt][2] * acc[mt][nt][2] + acc[mt][nt][3] * acc[mt][nt][3];
        }
        q0 += __shfl_xor_sync(0xffffffffu, q0, 1);
        q0 += __shfl_xor_sync(0xffffffffu, q0, 2);
        q1 += __shfl_xor_sync(0xffffffffu, q1, 1);
        q1 += __shfl_xor_sync(0xffffffffu, q1, 2);
        const float nr0 = sqrtf(q0), nr1 = sqrtf(q1);
        const float f0 = (q0 / (q0 + 1.0f)) / (nr0 + 1e-8f);
        const float f1 = (q1 / (q1 + 1.0f)) / (nr1 + 1e-8f);

        __half* u0 = g_uh + ((size_t)(n0 + r) * NI + i) * HH;
        __half* u1 = g_uh + ((size_t)(n0 + r + 8) * NI + i) * HH;
        #pragma unroll
        for (int nt = 0; nt < 8; ++nt) {
            const int h = nt * 8 + (l & 3) * 2;
            *reinterpret_cast<__half2*>(u0 + h) =
                __floats2half2_rn(acc[mt][nt][0] * f0, acc[mt][nt][1] * f0);
            *reinterpret_cast<__half2*>(u1 + h) =
                __floats2half2_rn(acc[mt][nt][2] * f1, acc[mt][nt][3] * f1);
        }
        if ((l & 3) == 0) {
            g_ai[(n0 + r) * NI + i]     = f0 * nr0;
            g_ai[(n0 + r + 8) * NI + i] = f1 * nr1;
        }
    }
}

// ============================================================
// K2 v5 (HMMA, fused Wv convert): block = (og, i); 8 o's per block.
// ============================================================
__global__ __launch_bounds__(256) void k_votes(const float* __restrict__ Wv,
                                               const float* __restrict__ Bv,
                                               const float* __restrict__ mask) {
    extern __shared__ __align__(16) unsigned char sm[];
    enum { SA = 0, SWF32 = 32768, SWF16 = 49152, SMASK = 57344, SBIAS = 58368, STG = 60416 };

    const int og = blockIdx.x, i = blockIdx.y;
    const int o0 = og * 8;
    const int t = threadIdx.x, w = t >> 5, l = t & 31;

    const uint32_t sA32  = smem_u32(sm + SA);
    const uint32_t sWF32 = smem_u32(sm + SWF32);
    const uint32_t sWF16 = smem_u32(sm + SWF16);
    float* smask = reinterpret_cast<float*>(sm + SMASK);
    float* sbias = reinterpret_cast<float*>(sm + SBIAS);

    const uint4* usrc = reinterpret_cast<const uint4*>(g_uh) + (size_t)i * 8;
    #pragma unroll
    for (int j = 0; j < 8; ++j) {
        const int idx = t + j * 256;
        const int n = idx >> 3, c = idx & 7;
        CP_ASYNC16(sA32 + n * 128 + ((c ^ (n & 7)) << 4), usrc + (size_t)n * (NI * 8) + c);
    }
    {
        const uint4* wsrc = reinterpret_cast<const uint4*>(
            Wv + ((size_t)(i * NO + o0)) * 4096);
        #pragma unroll
        for (int j = 0; j < 4; ++j) {
            const int idx = t + j * 256;
            CP_ASYNC16(sWF32 + idx * 16, wsrc + idx);
        }
    }
    CP_ASYNC_COMMIT();

    #pragma unroll
    for (int j = 0; j < 2; ++j) {
        const int idx = t + j * 256;
        sbias[idx] = Bv[(i * NO + o0 + (idx >> 6)) * HH + (idx & 63)];
    }
    smask[t] = mask[t * NI + i];

    for (int oo = 0; oo < 8; ++oo) {
        CP_ASYNC_WAIT0();
        __syncthreads();

        {
            const float2* wf32 = reinterpret_cast<const float2*>(sm + SWF32);
            __half2* wf16 = reinterpret_cast<__half2*>(sm + SWF16);
            #pragma unroll
            for (int j = 0; j < 8; ++j) {
                const int idx = t + j * 256;
                const int d = idx >> 5, h2 = idx & 31;
                const float2 f = wf32[idx];
                const int c = h2 >> 2;
                wf16[d * 32 + ((c ^ (d & 7)) << 2) + (h2 & 3)] =
                    __floats2half2_rn(f.x, f.y);
            }
        }
        __syncthreads();

        if (oo < 7) {
            const uint4* wsrc = reinterpret_cast<const uint4*>(
                Wv + ((size_t)(i * NO + o0 + oo + 1)) * 4096);
            #pragma unroll
            for (int j = 0; j < 4; ++j) {
                const int idx = t + j * 256;
                CP_ASYNC16(sWF32 + idx * 16, wsrc + idx);
            }
            CP_ASYNC_COMMIT();
        }

        float acc[2][8][4];
        #pragma unroll
        for (int mt = 0; mt < 2; ++mt)
            #pragma unroll
            for (int nt = 0; nt < 8; ++nt) {
                acc[mt][nt][0] = 0.f; acc[mt][nt][1] = 0.f;
                acc[mt][nt][2] = 0.f; acc[mt][nt][3] = 0.f;
            }

        #pragma unroll
        for (int k = 0; k < 4; ++k) {
            uint32_t a[2][4];
            #pragma unroll
            for (int mt = 0; mt < 2; ++mt) {
                const int row = w * 32 + mt * 16 + (l & 15);
                const int ch  = (k * 2 + (l >> 4)) ^ (row & 7);
                asm volatile("ldmatrix.sync.aligned.m8n8.x4.shared.b16 {%0,%1,%2,%3}, [%4];"
                    : "=r"(a[mt][0]), "=r"(a[mt][1]), "=r"(a[mt][2]), "=r"(a[mt][3])
                    : "r"(sA32 + row * 128 + ch * 16));
            }
            uint32_t b[8][2];
            #pragma unroll
            for (int nt = 0; nt < 8; ++nt) {
                const int d  = k * 16 + (l & 15);
                const int ch = nt ^ (d & 7);
                asm volatile("ldmatrix.sync.aligned.m8n8.x2.trans.shared.b16 {%0,%1}, [%2];"
                    : "=r"(b[nt][0]), "=r"(b[nt][1]) : "r"(sWF16 + d * 128 + ch * 16));
            }
            #pragma unroll
            for (int mt = 0; mt < 2; ++mt)
                #pragma unroll
                for (int nt = 0; nt < 8; ++nt)
                    asm volatile("mma.sync.aligned.m16n8k16.row.col.f32.f16.f16.f32 "
                        "{%0,%1,%2,%3}, {%4,%5,%6,%7}, {%8,%9}, {%0,%1,%2,%3};"
                        : "+f"(acc[mt][nt][0]), "+f"(acc[mt][nt][1]),
                          "+f"(acc[mt][nt][2]), "+f"(acc[mt][nt][3])
                        : "r"(a[mt][0]), "r"(a[mt][1]), "r"(a[mt][2]), "r"(a[mt][3]),
                          "r"(b[nt][0]), "r"(b[nt][1]));
        }

        __half2* stg = reinterpret_cast<__half2*>(sm + STG);
        const float* bo = sbias + oo * 64;
        #pragma unroll
        for (int mt = 0; mt < 2; ++mt) {
            const int r0 = w * 32 + mt * 16 + (l >> 2);
            #pragma unroll
            for (int nt = 0; nt < 8; ++nt) {
                const int h = nt * 8 + (l & 3) * 2;
                const float b0 = bo[h], b1 = bo[h + 1];
                stg[(r0 * 72 + h) >> 1] =
                    __floats2half2_rn(acc[mt][nt][0] + b0, acc[mt][nt][1] + b1);
                stg[((r0 + 8) * 72 + h) >> 1] =
                    __floats2half2_rn(acc[mt][nt][2] + b0, acc[mt][nt][3] + b1);
            }
        }
        __syncwarp();

        const int o = o0 + oo;
        #pragma unroll
        for (int p = 0; p < 8; ++p) {
            const int n = w * 32 + p * 4 + (l >> 3), c = l & 7;
            const __half2 mk2 = __float2half2_rn(smask[n]);
            uint4 v = *reinterpret_cast<const uint4*>(sm + STG + n * 144 + c * 16);
            __half2* vh = reinterpret_cast<__half2*>(&v);
            vh[0] = __hmul2(vh[0], mk2); vh[1] = __hmul2(vh[1], mk2);
            vh[2] = __hmul2(vh[2], mk2); vh[3] = __hmul2(vh[3], mk2);
            *reinterpret_cast<uint4*>(
                g_votes + ((size_t)(n * NI + i) * NO + o) * HH + c * 8) = v;
        }
        __syncwarp();
    }
}

// ============================================================
// K3 (persistent tensorized routing): b in smem, 2-stage cp.async.
// Agree: v-hi in B col0, v-lo in B col1 -> single MMA, agree = d0+d1.
// ============================================================
__global__ __launch_bounds__(256, 2) void k_route_all(float* __restrict__ out) {
    extern __shared__ __align__(16) uint4 dynbuf[];     // 2 x 2048 uint4 = 64 KB
    __shared__ __align__(16) __half svh[NO * HH];
    __shared__ __align__(16) __half svl[NO * HH];
    __shared__ float  sagree[NO * 8];
    __shared__ __half sct[NO * 8];
    __shared__ float  sai[NI];
    __shared__ float  sb_b[NI * NO];                    // 16 KB: b logits

    const int n = blockIdx.x;
    const int t = threadIdx.x, w = t >> 5, l = t & 31;

    if (t < NI) sai[t] = g_ai[n * NI + t];

    const uint4* vb = reinterpret_cast<const uint4*>(g_votes) + (size_t)n * (NI * NO * HH / 8);
    const uint32_t cbs[2] = { smem_u32(dynbuf), smem_u32(dynbuf + 2048) };

    for (int it = 0; it < 3; ++it) {
        float acc[4][4][4];
        #pragma unroll
        for (int oi = 0; oi < 4; ++oi)
            #pragma unroll
            for (int ht = 0; ht < 4; ++ht) {
                acc[oi][ht][0] = 0.f; acc[oi][ht][1] = 0.f;
                acc[oi][ht][2] = 0.f; acc[oi][ht][3] = 0.f;
            }

        {
            const uint4* src = vb;
            #pragma unroll
            for (int j = 0; j < 8; ++j) {
                const int idx = t + j * 256;
                const int r = idx >> 3, c = idx & 7;
                CP_ASYNC16(cbs[0] + (((r << 3) | (c ^ (r >> 5))) << 4), src + idx);
            }
            CP_ASYNC_COMMIT();
        }

        #pragma unroll 1
        for (int chk = 0; chk < 16; ++chk) {
            const uint32_t cb = cbs[chk & 1];
            CP_ASYNC_WAIT0();
            __syncthreads();

            if (chk < 15) {
                const uint32_t cbn = cbs[(chk + 1) & 1];
                const uint4* src = vb + (chk + 1) * 2048;
                #pragma unroll
                for (int j = 0; j < 8; ++j) {
                    const int idx = t + j * 256;
                    const int r = idx >> 3, c = idx & 7;
                    CP_ASYNC16(cbn + (((r << 3) | (c ^ (r >> 5))) << 4), src + idx);
                }
                CP_ASYNC_COMMIT();
            }

            if (it > 0) {
                #pragma unroll
                for (int oi = 0; oi < 4; ++oi) {
                    const int o = oi * 8 + w;
                    float d0 = 0.f, d1 = 0.f, d2 = 0.f, d3 = 0.f;
                    #pragma unroll
                    for (int k = 0; k < 4; ++k) {
                        const int il = l & 7;
                        const int r = il * 32 + o;
                        const int ch = (k * 2 + (l >> 4)) ^ il;
                        const uint32_t addr = cb + (((r << 3) + ch) << 4);
                        uint32_t a0, a1, a2, a3;
                        asm volatile("ldmatrix.sync.aligned.m8n8.x4.shared.b16 {%0,%1,%2,%3}, [%4];"
                            : "=r"(a0), "=r"(a1), "=r"(a2), "=r"(a3) : "r"(addr));
                        // B: col0 = v-hi (lanes 0-3), col1 = v-lo (lanes 4-7)
                        uint32_t b0 = 0, b1 = 0;
                        if (l < 4) {
                            b0 = *reinterpret_cast<const uint32_t*>(svh + o * 64 + k * 16 + l * 2);
                            b1 = *reinterpret_cast<const uint32_t*>(svh + o * 64 + k * 16 + 8 + l * 2);
                        } else if (l < 8) {
                            b0 = *reinterpret_cast<const uint32_t*>(svl + o * 64 + k * 16 + (l - 4) * 2);
                            b1 = *reinterpret_cast<const uint32_t*>(svl + o * 64 + k * 16 + 8 + (l - 4) * 2);
                        }
                        asm volatile("mma.sync.aligned.m16n8k16.row.col.f32.f16.f16.f32 "
                            "{%0,%1,%2,%3}, {%4,%5,%6,%7}, {%8,%9}, {%0,%1,%2,%3};"
                            : "+f"(d0), "+f"(d1), "+f"(d2), "+f"(d3)
                            : "r"(a0), "r"(a1), "r"(a2), "r"(a3), "r"(b0), "r"(b1));
                    }
                    if ((l & 3) == 0) sagree[o * 8 + (l >> 2)] = d0 + d1;
                }
                __syncthreads();

                {
                    const int i = chk * 8 + w;
                    const float ag = sagree[l * 8 + w];
                    float b = ag + (it == 2 ? sb_b[i * 32 + l] : 0.f);
                    if (it == 1) sb_b[i * 32 + l] = b;
                    float m = b;
                    #pragma unroll
                    for (int off = 16; off; off >>= 1)
                        m = fmaxf(m, __shfl_xor_sync(0xffffffffu, m, off));
                    m = fmaxf(m, 0.0f);
                    const float e = __expf(b - m);
                    float s = e;
                    #pragma unroll
                    for (int off = 16; off; off >>= 1)
                        s += __shfl_xor_sync(0xffffffffu, s, off);
                    s += __expf(-m);
                    sct[l * 8 + w] = __float2half(sai[i] * e / s);
                }
                __syncthreads();
            }

            #pragma unroll
            for (int oi = 0; oi < 4; ++oi) {
                const int o = oi * 8 + w;
                uint32_t bf = 0;
                if (l < 4) {
                    if (it == 0) {
                        const float c0 = sai[chk * 8 + l * 2]     * (1.0f / 33.0f);
                        const float c1 = sai[chk * 8 + l * 2 + 1] * (1.0f / 33.0f);
                        const __half2 hc = __floats2half2_rn(c0, c1);
                        bf = *reinterpret_cast<const uint32_t*>(&hc);
                    } else {
                        bf = *reinterpret_cast<const uint32_t*>(sct + o * 8 + l * 2);
                    }
                }
                #pragma unroll
                for (int ht = 0; ht < 4; ++ht) {
                    const int il = l & 7;
                    const int hc = (ht * 2 + ((l >> 3) & 1)) ^ il;
                    const int r = il * 32 + o;
                    const uint32_t addr = cb + (((r << 3) + hc) << 4);
                    uint32_t t0, t1;
                    asm volatile("ldmatrix.sync.aligned.m8n8.x2.trans.shared.b16 {%0,%1}, [%2];"
                        : "=r"(t0), "=r"(t1) : "r"(addr));
                    asm volatile("mma.sync.aligned.m16n8k8.row.col.f32.f16.f16.f32 "
                        "{%0,%1,%2,%3}, {%4,%5}, {%6}, {%0,%1,%2,%3};"
                        : "+f"(acc[oi][ht][0]), "+f"(acc[oi][ht][1]),
                          "+f"(acc[oi][ht][2]), "+f"(acc[oi][ht][3])
                        : "r"(t0), "r"(t1), "r"(bf));
                }
            }
        } // chunks

        #pragma unroll
        for (int oi = 0; oi < 4; ++oi) {
            const int o = oi * 8 + w;
            float q = 0.f;
            #pragma unroll
            for (int ht = 0; ht < 4; ++ht)
                q += acc[oi][ht][0] * acc[oi][ht][0] + acc[oi][ht][2] * acc[oi][ht][2];
            #pragma unroll
            for (int off = 16; off; off >>= 1)
                q += __shfl_xor_sync(0xffffffffu, q, off);
            const float nrm = sqrtf(q);
            const float f = (q / (q + 1.0f)) / (nrm + 1e-8f);

            if ((l & 3) == 0) {
                if (it < 2) {
                    #pragma unroll
                    for (int ht = 0; ht < 4; ++ht) {
                        const int h0 = ht * 16 + (l >> 2);
                        const float v0 = acc[oi][ht][0] * f;
                        const float v1 = acc[oi][ht][2] * f;
                        const __half hh0 = __float2half(v0);
                        const __half hh1 = __float2half(v1);
                        svh[o * 64 + h0] = hh0;
                        svl[o * 64 + h0] = __float2half(v0 - __half2float(hh0));
                        svh[o * 64 + h0 + 8] = hh1;
                        svl[o * 64 + h0 + 8] = __float2half(v1 - __half2float(hh1));
                    }
                } else {
                    #pragma unroll
                    for (int ht = 0; ht < 4; ++ht) {
                        const int h0 = ht * 16 + (l >> 2);
                        out[((size_t)n * NO + o) * HH + h0]     = acc[oi][ht][0] * f;
                        out[((size_t)n * NO + o) * HH + h0 + 8] = acc[oi][ht][2] * f;
                    }
                }
            }
        }
    } // iterations
}

// ============================================================
extern "C" void kernel_launch(void* const* d_in, const int* in_sizes, int n_in,
                              void* d_out, int out_size) {
    const float* x    = (const float*)d_in[0];
    const float* mask = (const float*)d_in[1];
    const float* Wcap = (const float*)d_in[2];
    const float* Bcap = (const float*)d_in[3];
    const float* Wv   = (const float*)d_in[4];
    const float* Bv   = (const float*)d_in[5];
    float* out = (float*)d_out;

    cudaFuncSetAttribute(k_u,         cudaFuncAttributeMaxDynamicSharedMemorySize, 49152);
    cudaFuncSetAttribute(k_votes,     cudaFuncAttributeMaxDynamicSharedMemorySize, 98304);
    cudaFuncSetAttribute(k_route_all, cudaFuncAttributeMaxDynamicSharedMemorySize, 65536);

    k_u        <<<dim3(2, 128),  128, 49152>>>(x, Wcap, Bcap);
    k_votes    <<<dim3(4, NI), 256, 98304>>>(Wv, Bv, mask);
    k_route_all<<<NB, 256, 65536>>>(out);
}

// round 16
// speedup vs baseline: 1.0510x; 1.0510x over previous
#include <cuda_runtime.h>
#include <cuda_fp16.h>
#include <stdint.h>
#include <math.h>

#define NB 256   // batch
#define NI 128   // input capsules
#define DD 256   // input feature dim
#define NO 32    // output capsules
#define HH 64    // in_dim == out_dim

// ---- scratch (device globals; no allocation allowed) ----
__device__ __half g_votes[(size_t)NB * NI * NO * HH];  // [n][i][o][h] fp16, 134 MB
__device__ __half g_uh[(size_t)NB * NI * HH];          // squashed u fp16, 4 MB
__device__ float  g_ai[NB * NI];                       // ||u||

__device__ __forceinline__ uint32_t smem_u32(const void* p) {
    uint32_t a;
    asm("{ .reg .u64 t; cvta.to.shared.u64 t, %1; cvt.u32.u64 %0, t; }" : "=r"(a) : "l"(p));
    return a;
}

#define CP_ASYNC16(dst_u32, src_ptr) \
    asm volatile("cp.async.cg.shared.global [%0], [%1], 16;" :: "r"(dst_u32), "l"(src_ptr))
#define CP_ASYNC_COMMIT() asm volatile("cp.async.commit_group;")
#define CP_ASYNC_WAIT0()  asm volatile("cp.async.wait_group 0;")

// ============================================================
// K1 (HMMA, hi/lo fp16 = fp32-accurate), M-tile = 128, cp.async staged.
// ============================================================
__global__ __launch_bounds__(128) void k_u(const float* __restrict__ x,
                                           const float* __restrict__ Wcap,
                                           const float* __restrict__ Bcap) {
    __shared__ __align__(16) __half sAhi[128 * 64];
    __shared__ __align__(16) __half sAlo[128 * 64];
    __shared__ __align__(16) __half sBhi[64 * 64];
    __shared__ __align__(16) __half sBlo[64 * 64];
    extern __shared__ __align__(16) unsigned char rawbuf[];   // 48 KB dynamic
    float* rawX = reinterpret_cast<float*>(rawbuf);
    float* rawW = reinterpret_cast<float*>(rawbuf + 32768);

    const int i  = blockIdx.y;
    const int n0 = blockIdx.x * 128;
    const int t  = threadIdx.x, w = t >> 5, l = t & 31;

    __half2* sAhi2 = reinterpret_cast<__half2*>(sAhi);
    __half2* sAlo2 = reinterpret_cast<__half2*>(sAlo);
    __half2* sBhi2 = reinterpret_cast<__half2*>(sBhi);
    __half2* sBlo2 = reinterpret_cast<__half2*>(sBlo);
    const uint32_t aHi = smem_u32(sAhi), aLo = smem_u32(sAlo);
    const uint32_t bHi = smem_u32(sBhi), bLo = smem_u32(sBlo);
    const uint32_t rX = smem_u32(rawX), rW = smem_u32(rawW);

    // prefetch kc = 0
    {
        #pragma unroll
        for (int j = 0; j < 16; ++j) {
            const int idx = t + j * 128;
            const int r = idx >> 4, c4 = idx & 15;
            CP_ASYNC16(rX + idx * 16,
                       reinterpret_cast<const uint4*>(
                           x + ((size_t)(n0 + r) * NI + i) * DD) + c4);
        }
        #pragma unroll
        for (int j = 0; j < 8; ++j) {
            const int idx = t + j * 128;
            const int d = idx >> 4, c4 = idx & 15;
            CP_ASYNC16(rW + idx * 16,
                       reinterpret_cast<const uint4*>(
                           Wcap + (size_t)i * DD * HH + (size_t)d * HH) + c4);
        }
        CP_ASYNC_COMMIT();
    }

    float acc[2][8][4];
    #pragma unroll
    for (int mt = 0; mt < 2; ++mt)
        #pragma unroll
        for (int nt = 0; nt < 8; ++nt) {
            acc[mt][nt][0] = 0.f; acc[mt][nt][1] = 0.f;
            acc[mt][nt][2] = 0.f; acc[mt][nt][3] = 0.f;
        }

    for (int kc = 0; kc < 4; ++kc) {
        CP_ASYNC_WAIT0();
        __syncthreads();

        {
            const float2* xr = reinterpret_cast<const float2*>(rawX);
            #pragma unroll
            for (int j = 0; j < 32; ++j) {
                const int idx = t + j * 128;
                const int r = idx >> 5, d2 = idx & 31;
                const float2 v = xr[idx];
                const __half h0 = __float2half_rn(v.x), h1 = __float2half_rn(v.y);
                const __half l0 = __float2half_rn(v.x - __half2float(h0));
                const __half l1 = __float2half_rn(v.y - __half2float(h1));
                const int c = d2 >> 2;
                const int sidx = r * 32 + ((c ^ (r & 7)) << 2) + (d2 & 3);
                sAhi2[sidx] = __halves2half2(h0, h1);
                sAlo2[sidx] = __halves2half2(l0, l1);
            }
            const float2* wr = reinterpret_cast<const float2*>(rawW);
            #pragma unroll
            for (int j = 0; j < 16; ++j) {
                const int idx = t + j * 128;
                const int d = idx >> 5, h2 = idx & 31;
                const float2 v = wr[idx];
                const __half h0 = __float2half_rn(v.x), h1 = __float2half_rn(v.y);
                const __half l0 = __float2half_rn(v.x - __half2float(h0));
                const __half l1 = __float2half_rn(v.y - __half2float(h1));
                const int c = h2 >> 2;
                const int sidx = d * 32 + ((c ^ (d & 7)) << 2) + (h2 & 3);
                sBhi2[sidx] = __halves2half2(h0, h1);
                sBlo2[sidx] = __halves2half2(l0, l1);
            }
        }
        __syncthreads();

        if (kc < 3) {
            const int ko = (kc + 1) * 64;
            #pragma unroll
            for (int j = 0; j < 16; ++j) {
                const int idx = t + j * 128;
                const int r = idx >> 4, c4 = idx & 15;
                CP_ASYNC16(rX + idx * 16,
                           reinterpret_cast<const uint4*>(
                               x + ((size_t)(n0 + r) * NI + i) * DD + ko) + c4);
            }
            #pragma unroll
            for (int j = 0; j < 8; ++j) {
                const int idx = t + j * 128;
                const int d = idx >> 4, c4 = idx & 15;
                CP_ASYNC16(rW + idx * 16,
                           reinterpret_cast<const uint4*>(
                               Wcap + (size_t)i * DD * HH + (size_t)(ko + d) * HH) + c4);
            }
            CP_ASYNC_COMMIT();
        }

        #pragma unroll
        for (int k = 0; k < 4; ++k) {
            uint32_t ah[2][4], al[2][4];
            #pragma unroll
            for (int mt = 0; mt < 2; ++mt) {
                const int row = w * 32 + mt * 16 + (l & 15);
                const int ch  = (k * 2 + (l >> 4)) ^ (row & 7);
                const uint32_t off = row * 128 + ch * 16;
                asm volatile("ldmatrix.sync.aligned.m8n8.x4.shared.b16 {%0,%1,%2,%3}, [%4];"
                    : "=r"(ah[mt][0]), "=r"(ah[mt][1]), "=r"(ah[mt][2]), "=r"(ah[mt][3])
                    : "r"(aHi + off));
                asm volatile("ldmatrix.sync.aligned.m8n8.x4.shared.b16 {%0,%1,%2,%3}, [%4];"
                    : "=r"(al[mt][0]), "=r"(al[mt][1]), "=r"(al[mt][2]), "=r"(al[mt][3])
                    : "r"(aLo + off));
            }
            #pragma unroll
            for (int nt = 0; nt < 8; ++nt) {
                const int d  = k * 16 + (l & 15);
                const int ch = nt ^ (d & 7);
                const uint32_t off = d * 128 + ch * 16;
                uint32_t bh0, bh1, bl0, bl1;
                asm volatile("ldmatrix.sync.aligned.m8n8.x2.trans.shared.b16 {%0,%1}, [%2];"
                    : "=r"(bh0), "=r"(bh1) : "r"(bHi + off));
                asm volatile("ldmatrix.sync.aligned.m8n8.x2.trans.shared.b16 {%0,%1}, [%2];"
                    : "=r"(bl0), "=r"(bl1) : "r"(bLo + off));
                #pragma unroll
                for (int mt = 0; mt < 2; ++mt) {
                    asm volatile("mma.sync.aligned.m16n8k16.row.col.f32.f16.f16.f32 "
                        "{%0,%1,%2,%3}, {%4,%5,%6,%7}, {%8,%9}, {%0,%1,%2,%3};"
                        : "+f"(acc[mt][nt][0]), "+f"(acc[mt][nt][1]),
                          "+f"(acc[mt][nt][2]), "+f"(acc[mt][nt][3])
                        : "r"(ah[mt][0]), "r"(ah[mt][1]), "r"(ah[mt][2]), "r"(ah[mt][3]),
                          "r"(bh0), "r"(bh1));
                    asm volatile("mma.sync.aligned.m16n8k16.row.col.f32.f16.f16.f32 "
                        "{%0,%1,%2,%3}, {%4,%5,%6,%7}, {%8,%9}, {%0,%1,%2,%3};"
                        : "+f"(acc[mt][nt][0]), "+f"(acc[mt][nt][1]),
                          "+f"(acc[mt][nt][2]), "+f"(acc[mt][nt][3])
                        : "r"(ah[mt][0]), "r"(ah[mt][1]), "r"(ah[mt][2]), "r"(ah[mt][3]),
                          "r"(bl0), "r"(bl1));
                    asm volatile("mma.sync.aligned.m16n8k16.row.col.f32.f16.f16.f32 "
                        "{%0,%1,%2,%3}, {%4,%5,%6,%7}, {%8,%9}, {%0,%1,%2,%3};"
                        : "+f"(acc[mt][nt][0]), "+f"(acc[mt][nt][1]),
                          "+f"(acc[mt][nt][2]), "+f"(acc[mt][nt][3])
                        : "r"(al[mt][0]), "r"(al[mt][1]), "r"(al[mt][2]), "r"(al[mt][3]),
                          "r"(bh0), "r"(bh1));
                }
            }
        }
    }

    #pragma unroll
    for (int mt = 0; mt < 2; ++mt) {
        const int r = w * 32 + mt * 16 + (l >> 2);
        float q0 = 0.f, q1 = 0.f;
        #pragma unroll
        for (int nt = 0; nt < 8; ++nt) {
            const float2 bv = *reinterpret_cast<const float2*>(
                Bcap + i * HH + nt * 8 + (l & 3) * 2);
            acc[mt][nt][0] += bv.x; acc[mt][nt][1] += bv.y;
            acc[mt][nt][2] += bv.x; acc[mt][nt][3] += bv.y;
            q0 += acc[mt][nt][0] * acc[mt][nt][0] + acc[mt][nt][1] * acc[mt][nt][1];
            q1 += acc[mt][nt][2] * acc[mt][nt][2] + acc[mt][nt][3] * acc[mt][nt][3];
        }
        q0 += __shfl_xor_sync(0xffffffffu, q0, 1);
        q0 += __shfl_xor_sync(0xffffffffu, q0, 2);
        q1 += __shfl_xor_sync(0xffffffffu, q1, 1);
        q1 += __shfl_xor_sync(0xffffffffu, q1, 2);
        const float nr0 = sqrtf(q0), nr1 = sqrtf(q1);
        const float f0 = (q0 / (q0 + 1.0f)) / (nr0 + 1e-8f);
        const float f1 = (q1 / (q1 + 1.0f)) / (nr1 + 1e-8f);

        __half* u0 = g_uh + ((size_t)(n0 + r) * NI + i) * HH;
        __half* u1 = g_uh + ((size_t)(n0 + r + 8) * NI + i) * HH;
        #pragma unroll
        for (int nt = 0; nt < 8; ++nt) {
            const int h = nt * 8 + (l & 3) * 2;
            *reinterpret_cast<__half2*>(u0 + h) =
                __floats2half2_rn(acc[mt][nt][0] * f0, acc[mt][nt][1] * f0);
            *reinterpret_cast<__half2*>(u1 + h) =
                __floats2half2_rn(acc[mt][nt][2] * f1, acc[mt][nt][3] * f1);
        }
        if ((l & 3) == 0) {
            g_ai[(n0 + r) * NI + i]     = f0 * nr0;
            g_ai[(n0 + r + 8) * NI + i] = f1 * nr1;
        }
    }
}

// ============================================================
// K2 v6 (HMMA, register-piped W convert): block = (og, i); 8 o's.
// W tile LDG'd into regs one oo ahead; convert regs -> wf16 double
// buffer; ONE __syncthreads per oo.
// ============================================================
__global__ __launch_bounds__(256) void k_votes(const float* __restrict__ Wv,
                                               const float* __restrict__ Bv,
                                               const float* __restrict__ mask) {
    extern __shared__ __align__(16) unsigned char sm[];
    enum { SA = 0, SWF16 = 32768, SMASK = 49152, SBIAS = 50176, STG = 52224 };
    // SWF16: 2 x 8 KB; STG: 36864 B; dyn total = 89088

    const int og = blockIdx.x, i = blockIdx.y;
    const int o0 = og * 8;
    const int t = threadIdx.x, w = t >> 5, l = t & 31;

    const uint32_t sA32  = smem_u32(sm + SA);
    const uint32_t sWF16 = smem_u32(sm + SWF16);
    float* smask = reinterpret_cast<float*>(sm + SMASK);
    float* sbias = reinterpret_cast<float*>(sm + SBIAS);

    // ---- async load sA: u[:, i, :] swizzled
    const uint4* usrc = reinterpret_cast<const uint4*>(g_uh) + (size_t)i * 8;
    #pragma unroll
    for (int j = 0; j < 8; ++j) {
        const int idx = t + j * 256;
        const int n = idx >> 3, c = idx & 7;
        CP_ASYNC16(sA32 + n * 128 + ((c ^ (n & 7)) << 4), usrc + (size_t)n * (NI * 8) + c);
    }
    CP_ASYNC_COMMIT();

    // ---- LDG W(0) into regs (coalesced float4)
    float4 wreg[4];
    {
        const float4* wsrc = reinterpret_cast<const float4*>(
            Wv + ((size_t)(i * NO + o0)) * 4096);
        #pragma unroll
        for (int j = 0; j < 4; ++j) wreg[j] = wsrc[t + j * 256];
    }

    // ---- bias (8 o's) + mask
    #pragma unroll
    for (int j = 0; j < 2; ++j) {
        const int idx = t + j * 256;
        sbias[idx] = Bv[(i * NO + o0 + (idx >> 6)) * HH + (idx & 63)];
    }
    smask[t] = mask[t * NI + i];

    CP_ASYNC_WAIT0();
    __syncthreads();   // sA resident

    for (int oo = 0; oo < 8; ++oo) {
        // ---- convert wreg (W tile oo) -> wf16[oo&1]
        {
            __half2* wf16 = reinterpret_cast<__half2*>(sm + SWF16 + (oo & 1) * 8192);
            #pragma unroll
            for (int j = 0; j < 4; ++j) {
                const int idx = t + j * 256;     // float4 id
                const int p = idx * 4;            // element id
                const int d = p >> 6;
                const int hp = (p & 63) >> 1;     // even half2 index
                const int c = hp >> 2;
                const int slot = d * 32 + ((c ^ (d & 7)) << 2) + (hp & 3);
                wf16[slot]     = __floats2half2_rn(wreg[j].x, wreg[j].y);
                wf16[slot + 1] = __floats2half2_rn(wreg[j].z, wreg[j].w);
            }
        }
        // ---- prefetch W(oo+1) into regs
        if (oo < 7) {
            const float4* wsrc = reinterpret_cast<const float4*>(
                Wv + ((size_t)(i * NO + o0 + oo + 1)) * 4096);
            #pragma unroll
            for (int j = 0; j < 4; ++j) wreg[j] = wsrc[t + j * 256];
        }
        __syncthreads();   // wf16[oo] visible to all warps

        const uint32_t sB32 = sWF16 + (oo & 1) * 8192;
        float acc[2][8][4];
        #pragma unroll
        for (int mt = 0; mt < 2; ++mt)
            #pragma unroll
            for (int nt = 0; nt < 8; ++nt) {
                acc[mt][nt][0] = 0.f; acc[mt][nt][1] = 0.f;
                acc[mt][nt][2] = 0.f; acc[mt][nt][3] = 0.f;
            }

        #pragma unroll
        for (int k = 0; k < 4; ++k) {
            uint32_t a[2][4];
            #pragma unroll
            for (int mt = 0; mt < 2; ++mt) {
                const int row = w * 32 + mt * 16 + (l & 15);
                const int ch  = (k * 2 + (l >> 4)) ^ (row & 7);
                asm volatile("ldmatrix.sync.aligned.m8n8.x4.shared.b16 {%0,%1,%2,%3}, [%4];"
                    : "=r"(a[mt][0]), "=r"(a[mt][1]), "=r"(a[mt][2]), "=r"(a[mt][3])
                    : "r"(sA32 + row * 128 + ch * 16));
            }
            uint32_t b[8][2];
            #pragma unroll
            for (int nt = 0; nt < 8; ++nt) {
                const int d  = k * 16 + (l & 15);
                const int ch = nt ^ (d & 7);
                asm volatile("ldmatrix.sync.aligned.m8n8.x2.trans.shared.b16 {%0,%1}, [%2];"
                    : "=r"(b[nt][0]), "=r"(b[nt][1]) : "r"(sB32 + d * 128 + ch * 16));
            }
            #pragma unroll
            for (int mt = 0; mt < 2; ++mt)
                #pragma unroll
                for (int nt = 0; nt < 8; ++nt)
                    asm volatile("mma.sync.aligned.m16n8k16.row.col.f32.f16.f16.f32 "
                        "{%0,%1,%2,%3}, {%4,%5,%6,%7}, {%8,%9}, {%0,%1,%2,%3};"
                        : "+f"(acc[mt][nt][0]), "+f"(acc[mt][nt][1]),
                          "+f"(acc[mt][nt][2]), "+f"(acc[mt][nt][3])
                        : "r"(a[mt][0]), "r"(a[mt][1]), "r"(a[mt][2]), "r"(a[mt][3]),
                          "r"(b[nt][0]), "r"(b[nt][1]));
        }

        // ---- warp-private stage (+bias), row stride 72 halfs
        __half2* stg = reinterpret_cast<__half2*>(sm + STG);
        const float* bo = sbias + oo * 64;
        #pragma unroll
        for (int mt = 0; mt < 2; ++mt) {
            const int r0 = w * 32 + mt * 16 + (l >> 2);
            #pragma unroll
            for (int nt = 0; nt < 8; ++nt) {
                const int h = nt * 8 + (l & 3) * 2;
                const float b0 = bo[h], b1 = bo[h + 1];
                stg[(r0 * 72 + h) >> 1] =
                    __floats2half2_rn(acc[mt][nt][0] + b0, acc[mt][nt][1] + b1);
                stg[((r0 + 8) * 72 + h) >> 1] =
                    __floats2half2_rn(acc[mt][nt][2] + b0, acc[mt][nt][3] + b1);
            }
        }
        __syncwarp();

        // ---- warp-private coalesced stores with mask (own 32 rows)
        const int o = o0 + oo;
        #pragma unroll
        for (int p = 0; p < 8; ++p) {
            const int n = w * 32 + p * 4 + (l >> 3), c = l & 7;
            const __half2 mk2 = __float2half2_rn(smask[n]);
            uint4 v = *reinterpret_cast<const uint4*>(sm + STG + n * 144 + c * 16);
            __half2* vh = reinterpret_cast<__half2*>(&v);
            vh[0] = __hmul2(vh[0], mk2); vh[1] = __hmul2(vh[1], mk2);
            vh[2] = __hmul2(vh[2], mk2); vh[3] = __hmul2(vh[3], mk2);
            *reinterpret_cast<uint4*>(
                g_votes + ((size_t)(n * NI + i) * NO + o) * HH + c * 8) = v;
        }
        __syncwarp();
    }
}

// ============================================================
// K3 (persistent tensorized routing, R14 version): b in smem,
// 2-stage cp.async, hi/lo agree via two chained MMAs.
// ============================================================
__global__ __launch_bounds__(256, 2) void k_route_all(float* __restrict__ out) {
    extern __shared__ __align__(16) uint4 dynbuf[];     // 2 x 2048 uint4 = 64 KB
    __shared__ __align__(16) __half svh[NO * HH];
    __shared__ __align__(16) __half svl[NO * HH];
    __shared__ float  sagree[NO * 8];
    __shared__ __half sct[NO * 8];
    __shared__ float  sai[NI];
    __shared__ float  sb_b[NI * NO];                    // 16 KB: b logits

    const int n = blockIdx.x;
    const int t = threadIdx.x, w = t >> 5, l = t & 31;

    if (t < NI) sai[t] = g_ai[n * NI + t];

    const uint4* vb = reinterpret_cast<const uint4*>(g_votes) + (size_t)n * (NI * NO * HH / 8);
    const uint32_t cbs[2] = { smem_u32(dynbuf), smem_u32(dynbuf + 2048) };

    for (int it = 0; it < 3; ++it) {
        float acc[4][4][4];
        #pragma unroll
        for (int oi = 0; oi < 4; ++oi)
            #pragma unroll
            for (int ht = 0; ht < 4; ++ht) {
                acc[oi][ht][0] = 0.f; acc[oi][ht][1] = 0.f;
                acc[oi][ht][2] = 0.f; acc[oi][ht][3] = 0.f;
            }

        {
            const uint4* src = vb;
            #pragma unroll
            for (int j = 0; j < 8; ++j) {
                const int idx = t + j * 256;
                const int r = idx >> 3, c = idx & 7;
                CP_ASYNC16(cbs[0] + (((r << 3) | (c ^ (r >> 5))) << 4), src + idx);
            }
            CP_ASYNC_COMMIT();
        }

        #pragma unroll 1
        for (int chk = 0; chk < 16; ++chk) {
            const uint32_t cb = cbs[chk & 1];
            CP_ASYNC_WAIT0();
            __syncthreads();

            if (chk < 15) {
                const uint32_t cbn = cbs[(chk + 1) & 1];
                const uint4* src = vb + (chk + 1) * 2048;
                #pragma unroll
                for (int j = 0; j < 8; ++j) {
                    const int idx = t + j * 256;
                    const int r = idx >> 3, c = idx & 7;
                    CP_ASYNC16(cbn + (((r << 3) | (c ^ (r >> 5))) << 4), src + idx);
                }
                CP_ASYNC_COMMIT();
            }

            if (it > 0) {
                #pragma unroll
                for (int oi = 0; oi < 4; ++oi) {
                    const int o = oi * 8 + w;
                    float d0 = 0.f, d1 = 0.f, d2 = 0.f, d3 = 0.f;
                    #pragma unroll
                    for (int k = 0; k < 4; ++k) {
                        const int il = l & 7;
                        const int r = il * 32 + o;
                        const int ch = (k * 2 + (l >> 4)) ^ il;
                        const uint32_t addr = cb + (((r << 3) + ch) << 4);
                        uint32_t a0, a1, a2, a3;
                        asm volatile("ldmatrix.sync.aligned.m8n8.x4.shared.b16 {%0,%1,%2,%3}, [%4];"
                            : "=r"(a0), "=r"(a1), "=r"(a2), "=r"(a3) : "r"(addr));
                        uint32_t b0 = 0, b1 = 0, c0 = 0, c1 = 0;
                        if (l < 4) {
                            b0 = *reinterpret_cast<const uint32_t*>(svh + o * 64 + k * 16 + l * 2);
                            b1 = *reinterpret_cast<const uint32_t*>(svh + o * 64 + k * 16 + 8 + l * 2);
                            c0 = *reinterpret_cast<const uint32_t*>(svl + o * 64 + k * 16 + l * 2);
                            c1 = *reinterpret_cast<const uint32_t*>(svl + o * 64 + k * 16 + 8 + l * 2);
                        }
                        asm volatile("mma.sync.aligned.m16n8k16.row.col.f32.f16.f16.f32 "
                            "{%0,%1,%2,%3}, {%4,%5,%6,%7}, {%8,%9}, {%0,%1,%2,%3};"
                            : "+f"(d0), "+f"(d1), "+f"(d2), "+f"(d3)
                            : "r"(a0), "r"(a1), "r"(a2), "r"(a3), "r"(b0), "r"(b1));
                        asm volatile("mma.sync.aligned.m16n8k16.row.col.f32.f16.f16.f32 "
                            "{%0,%1,%2,%3}, {%4,%5,%6,%7}, {%8,%9}, {%0,%1,%2,%3};"
                            : "+f"(d0), "+f"(d1), "+f"(d2), "+f"(d3)
                            : "r"(a0), "r"(a1), "r"(a2), "r"(a3), "r"(c0), "r"(c1));
                    }
                    if ((l & 3) == 0) sagree[o * 8 + (l >> 2)] = d0;
                }
                __syncthreads();

                {
                    const int i = chk * 8 + w;
                    const float ag = sagree[l * 8 + w];
                    float b = ag + (it == 2 ? sb_b[i * 32 + l] : 0.f);
                    if (it == 1) sb_b[i * 32 + l] = b;
                    float m = b;
                    #pragma unroll
                    for (int off = 16; off; off >>= 1)
                        m = fmaxf(m, __shfl_xor_sync(0xffffffffu, m, off));
                    m = fmaxf(m, 0.0f);
                    const float e = __expf(b - m);
                    float s = e;
                    #pragma unroll
                    for (int off = 16; off; off >>= 1)
                        s += __shfl_xor_sync(0xffffffffu, s, off);
                    s += __expf(-m);
                    sct[l * 8 + w] = __float2half(sai[i] * e / s);
                }
                __syncthreads();
            }

            #pragma unroll
            for (int oi = 0; oi < 4; ++oi) {
                const int o = oi * 8 + w;
                uint32_t bf = 0;
                if (l < 4) {
                    if (it == 0) {
                        const float c0 = sai[chk * 8 + l * 2]     * (1.0f / 33.0f);
                        const float c1 = sai[chk * 8 + l * 2 + 1] * (1.0f / 33.0f);
                        const __half2 hc = __floats2half2_rn(c0, c1);
                        bf = *reinterpret_cast<const uint32_t*>(&hc);
                    } else {
                        bf = *reinterpret_cast<const uint32_t*>(sct + o * 8 + l * 2);
                    }
                }
                #pragma unroll
                for (int ht = 0; ht < 4; ++ht) {
                    const int il = l & 7;
                    const int hc = (ht * 2 + ((l >> 3) & 1)) ^ il;
                    const int r = il * 32 + o;
                    const uint32_t addr = cb + (((r << 3) + hc) << 4);
                    uint32_t t0, t1;
                    asm volatile("ldmatrix.sync.aligned.m8n8.x2.trans.shared.b16 {%0,%1}, [%2];"
                        : "=r"(t0), "=r"(t1) : "r"(addr));
                    asm volatile("mma.sync.aligned.m16n8k8.row.col.f32.f16.f16.f32 "
                        "{%0,%1,%2,%3}, {%4,%5}, {%6}, {%0,%1,%2,%3};"
                        : "+f"(acc[oi][ht][0]), "+f"(acc[oi][ht][1]),
                          "+f"(acc[oi][ht][2]), "+f"(acc[oi][ht][3])
                        : "r"(t0), "r"(t1), "r"(bf));
                }
            }
        } // chunks

        #pragma unroll
        for (int oi = 0; oi < 4; ++oi) {
            const int o = oi * 8 + w;
            float q = 0.f;
            #pragma unroll
            for (int ht = 0; ht < 4; ++ht)
                q += acc[oi][ht][0] * acc[oi][ht][0] + acc[oi][ht][2] * acc[oi][ht][2];
            #pragma unroll
            for (int off = 16; off; off >>= 1)
                q += __shfl_xor_sync(0xffffffffu, q, off);
            const float nrm = sqrtf(q);
            const float f = (q / (q + 1.0f)) / (nrm + 1e-8f);

            if ((l & 3) == 0) {
                if (it < 2) {
                    #pragma unroll
                    for (int ht = 0; ht < 4; ++ht) {
                        const int h0 = ht * 16 + (l >> 2);
                        const float v0 = acc[oi][ht][0] * f;
                        const float v1 = acc[oi][ht][2] * f;
                        const __half hh0 = __float2half(v0);
                        const __half hh1 = __float2half(v1);
                        svh[o * 64 + h0] = hh0;
                        svl[o * 64 + h0] = __float2half(v0 - __half2float(hh0));
                        svh[o * 64 + h0 + 8] = hh1;
                        svl[o * 64 + h0 + 8] = __float2half(v1 - __half2float(hh1));
                    }
                } else {
                    #pragma unroll
                    for (int ht = 0; ht < 4; ++ht) {
                        const int h0 = ht * 16 + (l >> 2);
                        out[((size_t)n * NO + o) * HH + h0]     = acc[oi][ht][0] * f;
                        out[((size_t)n * NO + o) * HH + h0 + 8] = acc[oi][ht][2] * f;
                    }
                }
            }
        }
    } // iterations
}

// ============================================================
extern "C" void kernel_launch(void* const* d_in, const int* in_sizes, int n_in,
                              void* d_out, int out_size) {
    const float* x    = (const float*)d_in[0];
    const float* mask = (const float*)d_in[1];
    const float* Wcap = (const float*)d_in[2];
    const float* Bcap = (const float*)d_in[3];
    const float* Wv   = (const float*)d_in[4];
    const float* Bv   = (const float*)d_in[5];
    float* out = (float*)d_out;

    cudaFuncSetAttribute(k_u,         cudaFuncAttributeMaxDynamicSharedMemorySize, 49152);
    cudaFuncSetAttribute(k_votes,     cudaFuncAttributeMaxDynamicSharedMemorySize, 89088);
    cudaFuncSetAttribute(k_route_all, cudaFuncAttributeMaxDynamicSharedMemorySize, 65536);

    k_u        <<<dim3(2, 128),  128, 49152>>>(x, Wcap, Bcap);
    k_votes    <<<dim3(4, NI), 256, 89088>>>(Wv, Bv, mask);
    k_route_all<<<NB, 256, 65536>>>(out);
}

// round 17
// speedup vs baseline: 1.1121x; 1.0581x over previous
#include <cuda_runtime.h>
#include <cuda_fp16.h>
#include <stdint.h>
#include <math.h>

#define NB 256   // batch
#define NI 128   // input capsules
#define DD 256   // input feature dim
#define NO 32    // output capsules
#define HH 64    // in_dim == out_dim

// ---- scratch (device globals; no allocation allowed) ----
__device__ __half g_votes[(size_t)NB * NI * NO * HH];  // [n][i][o][h] fp16, 134 MB
__device__ __half g_uh[(size_t)NB * NI * HH];          // squashed u fp16, 4 MB
__device__ float  g_ai[NB * NI];                       // ||u||

__device__ __forceinline__ uint32_t smem_u32(const void* p) {
    uint32_t a;
    asm("{ .reg .u64 t; cvta.to.shared.u64 t, %1; cvt.u32.u64 %0, t; }" : "=r"(a) : "l"(p));
    return a;
}

#define CP_ASYNC16(dst_u32, src_ptr) \
    asm volatile("cp.async.cg.shared.global [%0], [%1], 16;" :: "r"(dst_u32), "l"(src_ptr))
#define CP_ASYNC_COMMIT() asm volatile("cp.async.commit_group;")
#define CP_ASYNC_WAIT0()  asm volatile("cp.async.wait_group 0;")

// ============================================================
// K1 (HMMA): u = squash(x @ Wcap + Bcap) -> fp16, ai = ||u||.
// x as fp16-hi only (error ~2.4e-4 rms); Wcap as hi/lo pair.
// D += Ahi*Bhi + Ahi*Blo. M-tile = 128, cp.async staged.
// ============================================================
__global__ __launch_bounds__(128) void k_u(const float* __restrict__ x,
                                           const float* __restrict__ Wcap,
                                           const float* __restrict__ Bcap) {
    __shared__ __align__(16) __half sAhi[128 * 64];   // 16 KB
    __shared__ __align__(16) __half sBhi[64 * 64];    // 8 KB
    __shared__ __align__(16) __half sBlo[64 * 64];    // 8 KB
    extern __shared__ __align__(16) unsigned char rawbuf[];   // 48 KB dynamic
    float* rawX = reinterpret_cast<float*>(rawbuf);
    float* rawW = reinterpret_cast<float*>(rawbuf + 32768);

    const int i  = blockIdx.y;
    const int n0 = blockIdx.x * 128;
    const int t  = threadIdx.x, w = t >> 5, l = t & 31;

    __half2* sAhi2 = reinterpret_cast<__half2*>(sAhi);
    __half2* sBhi2 = reinterpret_cast<__half2*>(sBhi);
    __half2* sBlo2 = reinterpret_cast<__half2*>(sBlo);
    const uint32_t aHi = smem_u32(sAhi);
    const uint32_t bHi = smem_u32(sBhi), bLo = smem_u32(sBlo);
    const uint32_t rX = smem_u32(rawX), rW = smem_u32(rawW);

    // prefetch kc = 0
    {
        #pragma unroll
        for (int j = 0; j < 16; ++j) {
            const int idx = t + j * 128;
            const int r = idx >> 4, c4 = idx & 15;
            CP_ASYNC16(rX + idx * 16,
                       reinterpret_cast<const uint4*>(
                           x + ((size_t)(n0 + r) * NI + i) * DD) + c4);
        }
        #pragma unroll
        for (int j = 0; j < 8; ++j) {
            const int idx = t + j * 128;
            const int d = idx >> 4, c4 = idx & 15;
            CP_ASYNC16(rW + idx * 16,
                       reinterpret_cast<const uint4*>(
                           Wcap + (size_t)i * DD * HH + (size_t)d * HH) + c4);
        }
        CP_ASYNC_COMMIT();
    }

    float acc[2][8][4];
    #pragma unroll
    for (int mt = 0; mt < 2; ++mt)
        #pragma unroll
        for (int nt = 0; nt < 8; ++nt) {
            acc[mt][nt][0] = 0.f; acc[mt][nt][1] = 0.f;
            acc[mt][nt][2] = 0.f; acc[mt][nt][3] = 0.f;
        }

    for (int kc = 0; kc < 4; ++kc) {
        CP_ASYNC_WAIT0();
        __syncthreads();

        {
            const float2* xr = reinterpret_cast<const float2*>(rawX);
            #pragma unroll
            for (int j = 0; j < 32; ++j) {
                const int idx = t + j * 128;
                const int r = idx >> 5, d2 = idx & 31;
                const float2 v = xr[idx];
                const int c = d2 >> 2;
                const int sidx = r * 32 + ((c ^ (r & 7)) << 2) + (d2 & 3);
                sAhi2[sidx] = __floats2half2_rn(v.x, v.y);
            }
            const float2* wr = reinterpret_cast<const float2*>(rawW);
            #pragma unroll
            for (int j = 0; j < 16; ++j) {
                const int idx = t + j * 128;
                const int d = idx >> 5, h2 = idx & 31;
                const float2 v = wr[idx];
                const __half h0 = __float2half_rn(v.x), h1 = __float2half_rn(v.y);
                const __half l0 = __float2half_rn(v.x - __half2float(h0));
                const __half l1 = __float2half_rn(v.y - __half2float(h1));
                const int c = h2 >> 2;
                const int sidx = d * 32 + ((c ^ (d & 7)) << 2) + (h2 & 3);
                sBhi2[sidx] = __halves2half2(h0, h1);
                sBlo2[sidx] = __halves2half2(l0, l1);
            }
        }
        __syncthreads();

        if (kc < 3) {
            const int ko = (kc + 1) * 64;
            #pragma unroll
            for (int j = 0; j < 16; ++j) {
                const int idx = t + j * 128;
                const int r = idx >> 4, c4 = idx & 15;
                CP_ASYNC16(rX + idx * 16,
                           reinterpret_cast<const uint4*>(
                               x + ((size_t)(n0 + r) * NI + i) * DD + ko) + c4);
            }
            #pragma unroll
            for (int j = 0; j < 8; ++j) {
                const int idx = t + j * 128;
                const int d = idx >> 4, c4 = idx & 15;
                CP_ASYNC16(rW + idx * 16,
                           reinterpret_cast<const uint4*>(
                               Wcap + (size_t)i * DD * HH + (size_t)(ko + d) * HH) + c4);
            }
            CP_ASYNC_COMMIT();
        }

        #pragma unroll
        for (int k = 0; k < 4; ++k) {
            uint32_t ah[2][4];
            #pragma unroll
            for (int mt = 0; mt < 2; ++mt) {
                const int row = w * 32 + mt * 16 + (l & 15);
                const int ch  = (k * 2 + (l >> 4)) ^ (row & 7);
                const uint32_t off = row * 128 + ch * 16;
                asm volatile("ldmatrix.sync.aligned.m8n8.x4.shared.b16 {%0,%1,%2,%3}, [%4];"
                    : "=r"(ah[mt][0]), "=r"(ah[mt][1]), "=r"(ah[mt][2]), "=r"(ah[mt][3])
                    : "r"(aHi + off));
            }
            #pragma unroll
            for (int nt = 0; nt < 8; ++nt) {
                const int d  = k * 16 + (l & 15);
                const int ch = nt ^ (d & 7);
                const uint32_t off = d * 128 + ch * 16;
                uint32_t bh0, bh1, bl0, bl1;
                asm volatile("ldmatrix.sync.aligned.m8n8.x2.trans.shared.b16 {%0,%1}, [%2];"
                    : "=r"(bh0), "=r"(bh1) : "r"(bHi + off));
                asm volatile("ldmatrix.sync.aligned.m8n8.x2.trans.shared.b16 {%0,%1}, [%2];"
                    : "=r"(bl0), "=r"(bl1) : "r"(bLo + off));
                #pragma unroll
                for (int mt = 0; mt < 2; ++mt) {
                    asm volatile("mma.sync.aligned.m16n8k16.row.col.f32.f16.f16.f32 "
                        "{%0,%1,%2,%3}, {%4,%5,%6,%7}, {%8,%9}, {%0,%1,%2,%3};"
                        : "+f"(acc[mt][nt][0]), "+f"(acc[mt][nt][1]),
                          "+f"(acc[mt][nt][2]), "+f"(acc[mt][nt][3])
                        : "r"(ah[mt][0]), "r"(ah[mt][1]), "r"(ah[mt][2]), "r"(ah[mt][3]),
                          "r"(bh0), "r"(bh1));
                    asm volatile("mma.sync.aligned.m16n8k16.row.col.f32.f16.f16.f32 "
                        "{%0,%1,%2,%3}, {%4,%5,%6,%7}, {%8,%9}, {%0,%1,%2,%3};"
                        : "+f"(acc[mt][nt][0]), "+f"(acc[mt][nt][1]),
                          "+f"(acc[mt][nt][2]), "+f"(acc[mt][nt][3])
                        : "r"(ah[mt][0]), "r"(ah[mt][1]), "r"(ah[mt][2]), "r"(ah[mt][3]),
                          "r"(bl0), "r"(bl1));
                }
            }
        }
    }

    #pragma unroll
    for (int mt = 0; mt < 2; ++mt) {
        const int r = w * 32 + mt * 16 + (l >> 2);
        float q0 = 0.f, q1 = 0.f;
        #pragma unroll
        for (int nt = 0; nt < 8; ++nt) {
            const float2 bv = *reinterpret_cast<const float2*>(
                Bcap + i * HH + nt * 8 + (l & 3) * 2);
            acc[mt][nt][0] += bv.x; acc[mt][nt][1] += bv.y;
            acc[mt][nt][2] += bv.x; acc[mt][nt][3] += bv.y;
            q0 += acc[mt][nt][0] * acc[mt][nt][0] + acc[mt][nt][1] * acc[mt][nt][1];
            q1 += acc[mt][nt][2] * acc[mt][nt][2] + acc[mt][nt][3] * acc[mt][nt][3];
        }
        q0 += __shfl_xor_sync(0xffffffffu, q0, 1);
        q0 += __shfl_xor_sync(0xffffffffu, q0, 2);
        q1 += __shfl_xor_sync(0xffffffffu, q1, 1);
        q1 += __shfl_xor_sync(0xffffffffu, q1, 2);
        const float nr0 = sqrtf(q0), nr1 = sqrtf(q1);
        const float f0 = (q0 / (q0 + 1.0f)) / (nr0 + 1e-8f);
        const float f1 = (q1 / (q1 + 1.0f)) / (nr1 + 1e-8f);

        __half* u0 = g_uh + ((size_t)(n0 + r) * NI + i) * HH;
        __half* u1 = g_uh + ((size_t)(n0 + r + 8) * NI + i) * HH;
        #pragma unroll
        for (int nt = 0; nt < 8; ++nt) {
            const int h = nt * 8 + (l & 3) * 2;
            *reinterpret_cast<__half2*>(u0 + h) =
                __floats2half2_rn(acc[mt][nt][0] * f0, acc[mt][nt][1] * f0);
            *reinterpret_cast<__half2*>(u1 + h) =
                __floats2half2_rn(acc[mt][nt][2] * f1, acc[mt][nt][3] * f1);
        }
        if ((l & 3) == 0) {
            g_ai[(n0 + r) * NI + i]     = f0 * nr0;
            g_ai[(n0 + r + 8) * NI + i] = f1 * nr1;
        }
    }
}

// ============================================================
// K2 v5 (HMMA, fused Wv convert) — R14 measured-best version.
// ============================================================
__global__ __launch_bounds__(256) void k_votes(const float* __restrict__ Wv,
                                               const float* __restrict__ Bv,
                                               const float* __restrict__ mask) {
    extern __shared__ __align__(16) unsigned char sm[];
    enum { SA = 0, SWF32 = 32768, SWF16 = 49152, SMASK = 57344, SBIAS = 58368, STG = 60416 };

    const int og = blockIdx.x, i = blockIdx.y;
    const int o0 = og * 8;
    const int t = threadIdx.x, w = t >> 5, l = t & 31;

    const uint32_t sA32  = smem_u32(sm + SA);
    const uint32_t sWF32 = smem_u32(sm + SWF32);
    const uint32_t sWF16 = smem_u32(sm + SWF16);
    float* smask = reinterpret_cast<float*>(sm + SMASK);
    float* sbias = reinterpret_cast<float*>(sm + SBIAS);

    const uint4* usrc = reinterpret_cast<const uint4*>(g_uh) + (size_t)i * 8;
    #pragma unroll
    for (int j = 0; j < 8; ++j) {
        const int idx = t + j * 256;
        const int n = idx >> 3, c = idx & 7;
        CP_ASYNC16(sA32 + n * 128 + ((c ^ (n & 7)) << 4), usrc + (size_t)n * (NI * 8) + c);
    }
    {
        const uint4* wsrc = reinterpret_cast<const uint4*>(
            Wv + ((size_t)(i * NO + o0)) * 4096);
        #pragma unroll
        for (int j = 0; j < 4; ++j) {
            const int idx = t + j * 256;
            CP_ASYNC16(sWF32 + idx * 16, wsrc + idx);
        }
    }
    CP_ASYNC_COMMIT();

    #pragma unroll
    for (int j = 0; j < 2; ++j) {
        const int idx = t + j * 256;
        sbias[idx] = Bv[(i * NO + o0 + (idx >> 6)) * HH + (idx & 63)];
    }
    smask[t] = mask[t * NI + i];

    for (int oo = 0; oo < 8; ++oo) {
        CP_ASYNC_WAIT0();
        __syncthreads();

        {
            const float2* wf32 = reinterpret_cast<const float2*>(sm + SWF32);
            __half2* wf16 = reinterpret_cast<__half2*>(sm + SWF16);
            #pragma unroll
            for (int j = 0; j < 8; ++j) {
                const int idx = t + j * 256;
                const int d = idx >> 5, h2 = idx & 31;
                const float2 f = wf32[idx];
                const int c = h2 >> 2;
                wf16[d * 32 + ((c ^ (d & 7)) << 2) + (h2 & 3)] =
                    __floats2half2_rn(f.x, f.y);
            }
        }
        __syncthreads();

        if (oo < 7) {
            const uint4* wsrc = reinterpret_cast<const uint4*>(
                Wv + ((size_t)(i * NO + o0 + oo + 1)) * 4096);
            #pragma unroll
            for (int j = 0; j < 4; ++j) {
                const int idx = t + j * 256;
                CP_ASYNC16(sWF32 + idx * 16, wsrc + idx);
            }
            CP_ASYNC_COMMIT();
        }

        float acc[2][8][4];
        #pragma unroll
        for (int mt = 0; mt < 2; ++mt)
            #pragma unroll
            for (int nt = 0; nt < 8; ++nt) {
                acc[mt][nt][0] = 0.f; acc[mt][nt][1] = 0.f;
                acc[mt][nt][2] = 0.f; acc[mt][nt][3] = 0.f;
            }

        #pragma unroll
        for (int k = 0; k < 4; ++k) {
            uint32_t a[2][4];
            #pragma unroll
            for (int mt = 0; mt < 2; ++mt) {
                const int row = w * 32 + mt * 16 + (l & 15);
                const int ch  = (k * 2 + (l >> 4)) ^ (row & 7);
                asm volatile("ldmatrix.sync.aligned.m8n8.x4.shared.b16 {%0,%1,%2,%3}, [%4];"
                    : "=r"(a[mt][0]), "=r"(a[mt][1]), "=r"(a[mt][2]), "=r"(a[mt][3])
                    : "r"(sA32 + row * 128 + ch * 16));
            }
            uint32_t b[8][2];
            #pragma unroll
            for (int nt = 0; nt < 8; ++nt) {
                const int d  = k * 16 + (l & 15);
                const int ch = nt ^ (d & 7);
                asm volatile("ldmatrix.sync.aligned.m8n8.x2.trans.shared.b16 {%0,%1}, [%2];"
                    : "=r"(b[nt][0]), "=r"(b[nt][1]) : "r"(sWF16 + d * 128 + ch * 16));
            }
            #pragma unroll
            for (int mt = 0; mt < 2; ++mt)
                #pragma unroll
                for (int nt = 0; nt < 8; ++nt)
                    asm volatile("mma.sync.aligned.m16n8k16.row.col.f32.f16.f16.f32 "
                        "{%0,%1,%2,%3}, {%4,%5,%6,%7}, {%8,%9}, {%0,%1,%2,%3};"
                        : "+f"(acc[mt][nt][0]), "+f"(acc[mt][nt][1]),
                          "+f"(acc[mt][nt][2]), "+f"(acc[mt][nt][3])
                        : "r"(a[mt][0]), "r"(a[mt][1]), "r"(a[mt][2]), "r"(a[mt][3]),
                          "r"(b[nt][0]), "r"(b[nt][1]));
        }

        __half2* stg = reinterpret_cast<__half2*>(sm + STG);
        const float* bo = sbias + oo * 64;
        #pragma unroll
        for (int mt = 0; mt < 2; ++mt) {
            const int r0 = w * 32 + mt * 16 + (l >> 2);
            #pragma unroll
            for (int nt = 0; nt < 8; ++nt) {
                const int h = nt * 8 + (l & 3) * 2;
                const float b0 = bo[h], b1 = bo[h + 1];
                stg[(r0 * 72 + h) >> 1] =
                    __floats2half2_rn(acc[mt][nt][0] + b0, acc[mt][nt][1] + b1);
                stg[((r0 + 8) * 72 + h) >> 1] =
                    __floats2half2_rn(acc[mt][nt][2] + b0, acc[mt][nt][3] + b1);
            }
        }
        __syncwarp();

        const int o = o0 + oo;
        #pragma unroll
        for (int p = 0; p < 8; ++p) {
            const int n = w * 32 + p * 4 + (l >> 3), c = l & 7;
            const __half2 mk2 = __float2half2_rn(smask[n]);
            uint4 v = *reinterpret_cast<const uint4*>(sm + STG + n * 144 + c * 16);
            __half2* vh = reinterpret_cast<__half2*>(&v);
            vh[0] = __hmul2(vh[0], mk2); vh[1] = __hmul2(vh[1], mk2);
            vh[2] = __hmul2(vh[2], mk2); vh[3] = __hmul2(vh[3], mk2);
            *reinterpret_cast<uint4*>(
                g_votes + ((size_t)(n * NI + i) * NO + o) * HH + c * 8) = v;
        }
        __syncwarp();
    }
}

// ============================================================
// K3 (persistent tensorized routing, R14 version): b in smem,
// 2-stage cp.async, hi/lo agree via two chained MMAs.
// it0 bf pack hoisted out of the oi loop.
// ============================================================
__global__ __launch_bounds__(256, 2) void k_route_all(float* __restrict__ out) {
    extern __shared__ __align__(16) uint4 dynbuf[];     // 2 x 2048 uint4 = 64 KB
    __shared__ __align__(16) __half svh[NO * HH];
    __shared__ __align__(16) __half svl[NO * HH];
    __shared__ float  sagree[NO * 8];
    __shared__ __half sct[NO * 8];
    __shared__ float  sai[NI];
    __shared__ float  sb_b[NI * NO];                    // 16 KB: b logits

    const int n = blockIdx.x;
    const int t = threadIdx.x, w = t >> 5, l = t & 31;

    if (t < NI) sai[t] = g_ai[n * NI + t];

    const uint4* vb = reinterpret_cast<const uint4*>(g_votes) + (size_t)n * (NI * NO * HH / 8);
    const uint32_t cbs[2] = { smem_u32(dynbuf), smem_u32(dynbuf + 2048) };

    for (int it = 0; it < 3; ++it) {
        float acc[4][4][4];
        #pragma unroll
        for (int oi = 0; oi < 4; ++oi)
            #pragma unroll
            for (int ht = 0; ht < 4; ++ht) {
                acc[oi][ht][0] = 0.f; acc[oi][ht][1] = 0.f;
                acc[oi][ht][2] = 0.f; acc[oi][ht][3] = 0.f;
            }

        {
            const uint4* src = vb;
            #pragma unroll
            for (int j = 0; j < 8; ++j) {
                const int idx = t + j * 256;
                const int r = idx >> 3, c = idx & 7;
                CP_ASYNC16(cbs[0] + (((r << 3) | (c ^ (r >> 5))) << 4), src + idx);
            }
            CP_ASYNC_COMMIT();
        }

        #pragma unroll 1
        for (int chk = 0; chk < 16; ++chk) {
            const uint32_t cb = cbs[chk & 1];
            CP_ASYNC_WAIT0();
            __syncthreads();

            if (chk < 15) {
                const uint32_t cbn = cbs[(chk + 1) & 1];
                const uint4* src = vb + (chk + 1) * 2048;
                #pragma unroll
                for (int j = 0; j < 8; ++j) {
                    const int idx = t + j * 256;
                    const int r = idx >> 3, c = idx & 7;
                    CP_ASYNC16(cbn + (((r << 3) | (c ^ (r >> 5))) << 4), src + idx);
                }
                CP_ASYNC_COMMIT();
            }

            if (it > 0) {
                #pragma unroll
                for (int oi = 0; oi < 4; ++oi) {
                    const int o = oi * 8 + w;
                    float d0 = 0.f, d1 = 0.f, d2 = 0.f, d3 = 0.f;
                    #pragma unroll
                    for (int k = 0; k < 4; ++k) {
                        const int il = l & 7;
                        const int r = il * 32 + o;
                        const int ch = (k * 2 + (l >> 4)) ^ il;
                        const uint32_t addr = cb + (((r << 3) + ch) << 4);
                        uint32_t a0, a1, a2, a3;
                        asm volatile("ldmatrix.sync.aligned.m8n8.x4.shared.b16 {%0,%1,%2,%3}, [%4];"
                            : "=r"(a0), "=r"(a1), "=r"(a2), "=r"(a3) : "r"(addr));
                        uint32_t b0 = 0, b1 = 0, c0 = 0, c1 = 0;
                        if (l < 4) {
                            b0 = *reinterpret_cast<const uint32_t*>(svh + o * 64 + k * 16 + l * 2);
                            b1 = *reinterpret_cast<const uint32_t*>(svh + o * 64 + k * 16 + 8 + l * 2);
                            c0 = *reinterpret_cast<const uint32_t*>(svl + o * 64 + k * 16 + l * 2);
                            c1 = *reinterpret_cast<const uint32_t*>(svl + o * 64 + k * 16 + 8 + l * 2);
                        }
                        asm volatile("mma.sync.aligned.m16n8k16.row.col.f32.f16.f16.f32 "
                            "{%0,%1,%2,%3}, {%4,%5,%6,%7}, {%8,%9}, {%0,%1,%2,%3};"
                            : "+f"(d0), "+f"(d1), "+f"(d2), "+f"(d3)
                            : "r"(a0), "r"(a1), "r"(a2), "r"(a3), "r"(b0), "r"(b1));
                        asm volatile("mma.sync.aligned.m16n8k16.row.col.f32.f16.f16.f32 "
                            "{%0,%1,%2,%3}, {%4,%5,%6,%7}, {%8,%9}, {%0,%1,%2,%3};"
                            : "+f"(d0), "+f"(d1), "+f"(d2), "+f"(d3)
                            : "r"(a0), "r"(a1), "r"(a2), "r"(a3), "r"(c0), "r"(c1));
                    }
                    if ((l & 3) == 0) sagree[o * 8 + (l >> 2)] = d0;
                }
                __syncthreads();

                {
                    const int i = chk * 8 + w;
                    const float ag = sagree[l * 8 + w];
                    float b = ag + (it == 2 ? sb_b[i * 32 + l] : 0.f);
                    if (it == 1) sb_b[i * 32 + l] = b;
                    float m = b;
                    #pragma unroll
                    for (int off = 16; off; off >>= 1)
                        m = fmaxf(m, __shfl_xor_sync(0xffffffffu, m, off));
                    m = fmaxf(m, 0.0f);
                    const float e = __expf(b - m);
                    float s = e;
                    #pragma unroll
                    for (int off = 16; off; off >>= 1)
                        s += __shfl_xor_sync(0xffffffffu, s, off);
                    s += __expf(-m);
                    sct[l * 8 + w] = __float2half(sai[i] * e / s);
                }
                __syncthreads();
            }

            // it0 bf is o-independent: pack once per chunk
            uint32_t bf0 = 0;
            if (it == 0 && l < 4) {
                const float c0 = sai[chk * 8 + l * 2]     * (1.0f / 33.0f);
                const float c1 = sai[chk * 8 + l * 2 + 1] * (1.0f / 33.0f);
                const __half2 hc = __floats2half2_rn(c0, c1);
                bf0 = *reinterpret_cast<const uint32_t*>(&hc);
            }

            #pragma unroll
            for (int oi = 0; oi < 4; ++oi) {
                const int o = oi * 8 + w;
                uint32_t bf = bf0;
                if (it > 0 && l < 4)
                    bf = *reinterpret_cast<const uint32_t*>(sct + o * 8 + l * 2);
                #pragma unroll
                for (int ht = 0; ht < 4; ++ht) {
                    const int il = l & 7;
                    const int hc = (ht * 2 + ((l >> 3) & 1)) ^ il;
                    const int r = il * 32 + o;
                    const uint32_t addr = cb + (((r << 3) + hc) << 4);
                    uint32_t t0, t1;
                    asm volatile("ldmatrix.sync.aligned.m8n8.x2.trans.shared.b16 {%0,%1}, [%2];"
                        : "=r"(t0), "=r"(t1) : "r"(addr));
                    asm volatile("mma.sync.aligned.m16n8k8.row.col.f32.f16.f16.f32 "
                        "{%0,%1,%2,%3}, {%4,%5}, {%6}, {%0,%1,%2,%3};"
                        : "+f"(acc[oi][ht][0]), "+f"(acc[oi][ht][1]),
                          "+f"(acc[oi][ht][2]), "+f"(acc[oi][ht][3])
                        : "r"(t0), "r"(t1), "r"(bf));
                }
            }
        } // chunks

        #pragma unroll
        for (int oi = 0; oi < 4; ++oi) {
            const int o = oi * 8 + w;
            float q = 0.f;
            #pragma unroll
            for (int ht = 0; ht < 4; ++ht)
                q += acc[oi][ht][0] * acc[oi][ht][0] + acc[oi][ht][2] * acc[oi][ht][2];
            #pragma unroll
            for (int off = 16; off; off >>= 1)
                q += __shfl_xor_sync(0xffffffffu, q, off);
            const float nrm = sqrtf(q);
            const float f = (q / (q + 1.0f)) / (nrm + 1e-8f);

            if ((l & 3) == 0) {
                if (it < 2) {
                    #pragma unroll
                    for (int ht = 0; ht < 4; ++ht) {
                        const int h0 = ht * 16 + (l >> 2);
                        const float v0 = acc[oi][ht][0] * f;
                        const float v1 = acc[oi][ht][2] * f;
                        const __half hh0 = __float2half(v0);
                        const __half hh1 = __float2half(v1);
                        svh[o * 64 + h0] = hh0;
                        svl[o * 64 + h0] = __float2half(v0 - __half2float(hh0));
                        svh[o * 64 + h0 + 8] = hh1;
                        svl[o * 64 + h0 + 8] = __float2half(v1 - __half2float(hh1));
                    }
                } else {
                    #pragma unroll
                    for (int ht = 0; ht < 4; ++ht) {
                        const int h0 = ht * 16 + (l >> 2);
                        out[((size_t)n * NO + o) * HH + h0]     = acc[oi][ht][0] * f;
                        out[((size_t)n * NO + o) * HH + h0 + 8] = acc[oi][ht][2] * f;
                    }
                }
            }
        }
    } // iterations
}

// ============================================================
extern "C" void kernel_launch(void* const* d_in, const int* in_sizes, int n_in,
                              void* d_out, int out_size) {
    const float* x    = (const float*)d_in[0];
    const float* mask = (const float*)d_in[1];
    const float* Wcap = (const float*)d_in[2];
    const float* Bcap = (const float*)d_in[3];
    const float* Wv   = (const float*)d_in[4];
    const float* Bv   = (const float*)d_in[5];
    float* out = (float*)d_out;

    cudaFuncSetAttribute(k_u,         cudaFuncAttributeMaxDynamicSharedMemorySize, 49152);
    cudaFuncSetAttribute(k_votes,     cudaFuncAttributeMaxDynamicSharedMemorySize, 98304);
    cudaFuncSetAttribute(k_route_all, cudaFuncAttributeMaxDynamicSharedMemorySize, 65536);

    k_u        <<<dim3(2, 128),  128, 49152>>>(x, Wcap, Bcap);
    k_votes    <<<dim3(4, NI), 256, 98304>>>(Wv, Bv, mask);
    k_route_all<<<NB, 256, 65536>>>(out);
}